// round 9
// baseline (speedup 1.0000x reference)
#include <cuda_runtime.h>
#include <cuda_bf16.h>
#include <cstdint>

#define B_   32
#define S_   512
#define E_   8
#define H_   768
#define KG_  100
#define MH_  1000
#define NROW 256
#define MHP  1024            /* padded hidden (k2 K dim) */
#define KP1  120             /* k1 smem k-pitch (112 used) */
#define KP2  264             /* k2 smem k-pitch (256 used) */

// Scratch (device globals — no allocation allowed)
__device__ __align__(16) __nv_bfloat16 g_Hs_hi[NROW * MHP];
__device__ __align__(16) __nv_bfloat16 g_Hs_lo[NROW * MHP];
__device__ __align__(16) __nv_bfloat16 g_W2h[H_ * MHP];   // [n][k] transposed
__device__ __align__(16) __nv_bfloat16 g_W2l[H_ * MHP];
__device__ __align__(16) float g_ENT[NROW * H_];

// ---------------- helpers ---------------------------------------------------
__device__ __forceinline__ uint32_t smem_u32(const void* p) {
    uint32_t a;
    asm("{ .reg .u64 t; cvta.to.shared.u64 t, %1; cvt.u32.u64 %0, t; }"
        : "=r"(a) : "l"(p));
    return a;
}
__device__ __forceinline__ void splitbf(float x, unsigned short& h,
                                        unsigned short& l) {
    __nv_bfloat16 hb = __float2bfloat16(x);
    float r = x - __bfloat162float(hb);
    __nv_bfloat16 lb = __float2bfloat16(r);
    h = *(unsigned short*)&hb;
    l = *(unsigned short*)&lb;
}
__device__ __forceinline__ void ldm_x4(uint32_t* r, uint32_t addr) {
    asm volatile("ldmatrix.sync.aligned.m8n8.x4.shared.b16 {%0,%1,%2,%3}, [%4];"
                 : "=r"(r[0]), "=r"(r[1]), "=r"(r[2]), "=r"(r[3]) : "r"(addr));
}
__device__ __forceinline__ void ldm_x2(uint32_t* r, uint32_t addr) {
    asm volatile("ldmatrix.sync.aligned.m8n8.x2.shared.b16 {%0,%1}, [%2];"
                 : "=r"(r[0]), "=r"(r[1]) : "r"(addr));
}
__device__ __forceinline__ void mma16816(float* c, const uint32_t* a,
                                         const uint32_t* b) {
    asm volatile(
        "mma.sync.aligned.m16n8k16.row.col.f32.bf16.bf16.f32 "
        "{%0,%1,%2,%3}, {%4,%5,%6,%7}, {%8,%9}, {%0,%1,%2,%3};"
        : "+f"(c[0]), "+f"(c[1]), "+f"(c[2]), "+f"(c[3])
        : "r"(a[0]), "r"(a[1]), "r"(a[2]), "r"(a[3]), "r"(b[0]), "r"(b[1]));
}

// ---------------------------------------------------------------------------
// kw: W2 [1000,768] fp32 -> transposed split bf16 g_W2h/l [768][1024]
// grid (32, 24): 32x32 tiles (k, n). block (32, 8). k pad zero-filled.
// ---------------------------------------------------------------------------
__global__ void __launch_bounds__(256) kw_split(const float* __restrict__ W2) {
    __shared__ unsigned short sh[32][34], sl[32][34];
    const int k0 = blockIdx.x * 32;
    const int n0 = blockIdx.y * 32;
    const int tx = threadIdx.x, ty = threadIdx.y;

    #pragma unroll
    for (int j = 0; j < 4; j++) {
        int k = k0 + ty + j * 8;
        float v = (k < MH_) ? __ldg(W2 + (long long)k * H_ + n0 + tx) : 0.0f;
        unsigned short h, l;
        splitbf(v, h, l);
        sh[ty + j * 8][tx] = h;
        sl[ty + j * 8][tx] = l;
    }
    __syncthreads();
    #pragma unroll
    for (int j = 0; j < 4; j++) {
        int nn = ty + j * 8;
        g_W2h[(long long)(n0 + nn) * MHP + k0 + tx] =
            *(__nv_bfloat16*)&sh[tx][nn];
        g_W2l[(long long)(n0 + nn) * MHP + k0 + tx] =
            *(__nv_bfloat16*)&sl[tx][nn];
    }
}

// ---------------------------------------------------------------------------
// K1 (HMMA): Hs = relu(X @ W1 + b1) -> pre-split bf16 hi/lo [256][1024]
// grid (8, 8): M tile 32, N tile 128. block 128 (4 warps, each N-slice 32).
// K = 100 padded to 112 (7 k16 steps).
// ---------------------------------------------------------------------------
#define SM1_AL (32 * KP1 * 2)            /* 7680  */
#define SM1_BH (2 * SM1_AL)              /* 15360 */
#define SM1_BL (SM1_BH + 128 * KP1 * 2)  /* 46080 */
#define SMEM1  (SM1_BL + 128 * KP1 * 2)  /* 76800 */

__global__ void __launch_bounds__(128) k1_mma(const float* __restrict__ X,
                                              const float* __restrict__ W1,
                                              const float* __restrict__ b1) {
    extern __shared__ char dsm[];
    const uint32_t sb = smem_u32(dsm);
    __nv_bfloat16* Ah = (__nv_bfloat16*)dsm;
    __nv_bfloat16* Al = (__nv_bfloat16*)(dsm + SM1_AL);
    __nv_bfloat16* Bh = (__nv_bfloat16*)(dsm + SM1_BH);
    __nv_bfloat16* Bl = (__nv_bfloat16*)(dsm + SM1_BL);

    const int tid = threadIdx.x;
    const int lane = tid & 31, wid = tid >> 5;
    const int rb = blockIdx.x * 32;
    const int n0 = blockIdx.y * 128;

    // Stage A = X rows (fp32 -> hi/lo), k zero-padded to 120
    for (int idx = tid; idx < 32 * KP1; idx += 128) {
        int r = idx / KP1, k = idx - r * KP1;
        float v = (k < KG_) ? __ldg(X + (rb + r) * KG_ + k) : 0.0f;
        unsigned short h, l;
        splitbf(v, h, l);
        Ah[r * KP1 + k] = *(__nv_bfloat16*)&h;
        Al[r * KP1 + k] = *(__nv_bfloat16*)&l;
    }
    // Stage B[n][k] = W1[k][n0+n] (coalesced reads over n)
    for (int idx = tid; idx < 128 * KP1; idx += 128) {
        int k = idx >> 7, n = idx & 127;
        float v = (k < KG_ && (n0 + n) < MH_) ? __ldg(W1 + k * MH_ + n0 + n) : 0.0f;
        unsigned short h, l;
        splitbf(v, h, l);
        Bh[n * KP1 + k] = *(__nv_bfloat16*)&h;
        Bl[n * KP1 + k] = *(__nv_bfloat16*)&l;
    }
    __syncthreads();

    const int n_w = wid * 32;
    float acc[2][4][4];
    #pragma unroll
    for (int i = 0; i < 2; i++)
        #pragma unroll
        for (int j = 0; j < 4; j++)
            #pragma unroll
            for (int q = 0; q < 4; q++) acc[i][j][q] = 0.0f;

    const uint32_t arow = lane & 15;
    const uint32_t akof = (lane >> 4) << 3;
    const uint32_t brow = lane & 7;
    const uint32_t bkof = ((lane >> 3) & 1) << 3;

    #pragma unroll
    for (int ks = 0; ks < 7; ks++) {
        const uint32_t kk = ks * 16;
        uint32_t ah[2][4], al[2][4], bh[4][2], bl[4][2];
        #pragma unroll
        for (int i = 0; i < 2; i++) {
            uint32_t ro = (i * 16 + arow) * KP1 + kk + akof;
            ldm_x4(ah[i], sb + ro * 2);
            ldm_x4(al[i], sb + SM1_AL + ro * 2);
        }
        #pragma unroll
        for (int j = 0; j < 4; j++) {
            uint32_t ro = (n_w + j * 8 + brow) * KP1 + kk + bkof;
            ldm_x2(bh[j], sb + SM1_BH + ro * 2);
            ldm_x2(bl[j], sb + SM1_BL + ro * 2);
        }
        #pragma unroll
        for (int i = 0; i < 2; i++)
            #pragma unroll
            for (int j = 0; j < 4; j++) {
                mma16816(acc[i][j], ah[i], bh[j]);
                mma16816(acc[i][j], ah[i], bl[j]);
                mma16816(acc[i][j], al[i], bh[j]);
            }
    }

    // Epilogue: +b1, relu, split, store hi/lo
    #pragma unroll
    for (int i = 0; i < 2; i++) {
        int row = rb + i * 16 + (lane >> 2);
        #pragma unroll
        for (int j = 0; j < 4; j++) {
            int col = n0 + n_w + j * 8 + (lane & 3) * 2;
            float bb0 = (col     < MH_) ? __ldg(b1 + col)     : 0.0f;
            float bb1 = (col + 1 < MH_) ? __ldg(b1 + col + 1) : 0.0f;
            float f0 = fmaxf(acc[i][j][0] + bb0, 0.0f);
            float f1 = fmaxf(acc[i][j][1] + bb1, 0.0f);
            float f2 = fmaxf(acc[i][j][2] + bb0, 0.0f);
            float f3 = fmaxf(acc[i][j][3] + bb1, 0.0f);
            if (col >= MH_) f0 = f1 = f2 = f3 = 0.0f;   // pad cols -> 0
            unsigned short h0, l0, h1, l1;
            splitbf(f0, h0, l0); splitbf(f1, h1, l1);
            *(uint32_t*)(g_Hs_hi + row * MHP + col) = (uint32_t)h0 | ((uint32_t)h1 << 16);
            *(uint32_t*)(g_Hs_lo + row * MHP + col) = (uint32_t)l0 | ((uint32_t)l1 << 16);
            splitbf(f2, h0, l0); splitbf(f3, h1, l1);
            *(uint32_t*)(g_Hs_hi + (row + 8) * MHP + col) = (uint32_t)h0 | ((uint32_t)h1 << 16);
            *(uint32_t*)(g_Hs_lo + (row + 8) * MHP + col) = (uint32_t)l0 | ((uint32_t)l1 << 16);
        }
    }
}

// ---------------------------------------------------------------------------
// K2 (HMMA): ENT = Hs(hi/lo bf16) @ W2T(hi/lo bf16) + b2
// grid (8, 6): M tile 32, N tile 128. block 128 (4 warps, N-slice 32).
// K = 1024 in 4 chunks of 256 staged in smem.
// ---------------------------------------------------------------------------
#define SM2_AL (32 * KP2 * 2)            /* 16896  */
#define SM2_BH (2 * SM2_AL)              /* 33792  */
#define SM2_BL (SM2_BH + 128 * KP2 * 2)  /* 101376 */
#define SMEM2  (SM2_BL + 128 * KP2 * 2)  /* 168960 */

__global__ void __launch_bounds__(128) k2_mma(const float* __restrict__ b2) {
    extern __shared__ char dsm[];
    const uint32_t sb = smem_u32(dsm);
    const int tid = threadIdx.x;
    const int lane = tid & 31, wid = tid >> 5;
    const int rb = blockIdx.x * 32;
    const int n0 = blockIdx.y * 128;
    const int n_w = wid * 32;

    float acc[2][4][4];
    #pragma unroll
    for (int i = 0; i < 2; i++)
        #pragma unroll
        for (int j = 0; j < 4; j++)
            #pragma unroll
            for (int q = 0; q < 4; q++) acc[i][j][q] = 0.0f;

    const uint32_t arow = lane & 15;
    const uint32_t akof = (lane >> 4) << 3;
    const uint32_t brow = lane & 7;
    const uint32_t bkof = ((lane >> 3) & 1) << 3;

    for (int ch = 0; ch < 4; ch++) {
        const int kb = ch * 256;
        if (ch) __syncthreads();

        // Stage A: 32 rows x 32 uint4 (hi & lo)
        for (int idx = tid; idx < 32 * 32; idx += 128) {
            int r = idx >> 5, c = idx & 31;
            uint4 vh = *(const uint4*)(g_Hs_hi + (rb + r) * MHP + kb + c * 8);
            uint4 vl = *(const uint4*)(g_Hs_lo + (rb + r) * MHP + kb + c * 8);
            *(uint4*)(dsm + (r * KP2 + c * 8) * 2)          = vh;
            *(uint4*)(dsm + SM2_AL + (r * KP2 + c * 8) * 2) = vl;
        }
        // Stage B: 128 rows x 32 uint4 (hi & lo)
        for (int idx = tid; idx < 128 * 32; idx += 128) {
            int n = idx >> 5, c = idx & 31;
            uint4 vh = *(const uint4*)(g_W2h + (long long)(n0 + n) * MHP + kb + c * 8);
            uint4 vl = *(const uint4*)(g_W2l + (long long)(n0 + n) * MHP + kb + c * 8);
            *(uint4*)(dsm + SM2_BH + (n * KP2 + c * 8) * 2) = vh;
            *(uint4*)(dsm + SM2_BL + (n * KP2 + c * 8) * 2) = vl;
        }
        __syncthreads();

        #pragma unroll 4
        for (int ks = 0; ks < 16; ks++) {
            const uint32_t kk = ks * 16;
            uint32_t ah[2][4], al[2][4], bh[4][2], bl[4][2];
            #pragma unroll
            for (int i = 0; i < 2; i++) {
                uint32_t ro = (i * 16 + arow) * KP2 + kk + akof;
                ldm_x4(ah[i], sb + ro * 2);
                ldm_x4(al[i], sb + SM2_AL + ro * 2);
            }
            #pragma unroll
            for (int j = 0; j < 4; j++) {
                uint32_t ro = (n_w + j * 8 + brow) * KP2 + kk + bkof;
                ldm_x2(bh[j], sb + SM2_BH + ro * 2);
                ldm_x2(bl[j], sb + SM2_BL + ro * 2);
            }
            #pragma unroll
            for (int i = 0; i < 2; i++)
                #pragma unroll
                for (int j = 0; j < 4; j++) {
                    mma16816(acc[i][j], ah[i], bh[j]);
                    mma16816(acc[i][j], ah[i], bl[j]);
                    mma16816(acc[i][j], al[i], bh[j]);
                }
        }
    }

    // Epilogue: +b2, store fp32 ENT
    #pragma unroll
    for (int i = 0; i < 2; i++) {
        int row = rb + i * 16 + (lane >> 2);
        #pragma unroll
        for (int j = 0; j < 4; j++) {
            int col = n0 + n_w + j * 8 + (lane & 3) * 2;
            float bb0 = __ldg(b2 + col), bb1 = __ldg(b2 + col + 1);
            float2 o0 = make_float2(acc[i][j][0] + bb0, acc[i][j][1] + bb1);
            float2 o1 = make_float2(acc[i][j][2] + bb0, acc[i][j][3] + bb1);
            *(float2*)(g_ENT + row * H_ + col)       = o0;
            *(float2*)(g_ENT + (row + 8) * H_ + col) = o1;
        }
    }
}

// ---------------------------------------------------------------------------
// K3: out = gather + masked entity add (round-4 form, 15.4us measured)
// ---------------------------------------------------------------------------
__global__ void __launch_bounds__(192) k3_fuse(const int*   __restrict__ ids,
                                               const float* __restrict__ mask,
                                               const float* __restrict__ we,
                                               float*       __restrict__ out) {
    const int rblk = blockIdx.x;          // 4096
    const int b    = rblk >> 7;
    const int s0   = (rblk & 127) << 2;
    const int row0 = b * S_ + s0;
    const int tid  = threadIdx.x;

    __shared__ float    sm[E_][4];
    __shared__ unsigned sflag;

    int wid0 = __ldg(ids + row0 + 0);
    int wid1 = __ldg(ids + row0 + 1);
    int wid2 = __ldg(ids + row0 + 2);
    int wid3 = __ldg(ids + row0 + 3);

    const float4* __restrict__ we4 = (const float4*)we;
    float4 v0 = we4[(long long)wid0 * (H_ / 4) + tid];
    float4 v1 = we4[(long long)wid1 * (H_ / 4) + tid];
    float4 v2 = we4[(long long)wid2 * (H_ / 4) + tid];
    float4 v3 = we4[(long long)wid3 * (H_ / 4) + tid];

    if (tid < 32) {
        int e  = tid >> 2;
        int rr = tid & 3;
        float m = __ldg(mask + (b * E_ + e) * S_ + s0 + rr);
        sm[e][rr] = m;
        unsigned bal = __ballot_sync(0xffffffffu, m != 0.0f);
        if (tid == 0) sflag = bal;
    }
    __syncthreads();

    const unsigned flag = sflag;
    if (flag) {
        const float4* __restrict__ ent4 = (const float4*)g_ENT;
        #pragma unroll
        for (int e = 0; e < E_; e++) {
            unsigned f4 = (flag >> (e * 4)) & 0xFu;
            if (f4) {
                float4 p = ent4[(b * E_ + e) * (H_ / 4) + tid];
                if (f4 & 1u) { float m = sm[e][0];
                    v0.x = fmaf(m, p.x, v0.x); v0.y = fmaf(m, p.y, v0.y);
                    v0.z = fmaf(m, p.z, v0.z); v0.w = fmaf(m, p.w, v0.w); }
                if (f4 & 2u) { float m = sm[e][1];
                    v1.x = fmaf(m, p.x, v1.x); v1.y = fmaf(m, p.y, v1.y);
                    v1.z = fmaf(m, p.z, v1.z); v1.w = fmaf(m, p.w, v1.w); }
                if (f4 & 4u) { float m = sm[e][2];
                    v2.x = fmaf(m, p.x, v2.x); v2.y = fmaf(m, p.y, v2.y);
                    v2.z = fmaf(m, p.z, v2.z); v2.w = fmaf(m, p.w, v2.w); }
                if (f4 & 8u) { float m = sm[e][3];
                    v3.x = fmaf(m, p.x, v3.x); v3.y = fmaf(m, p.y, v3.y);
                    v3.z = fmaf(m, p.z, v3.z); v3.w = fmaf(m, p.w, v3.w); }
            }
        }
    }

    float4* __restrict__ out4 = (float4*)out;
    out4[(long long)(row0 + 0) * (H_ / 4) + tid] = v0;
    out4[(long long)(row0 + 1) * (H_ / 4) + tid] = v1;
    out4[(long long)(row0 + 2) * (H_ / 4) + tid] = v2;
    out4[(long long)(row0 + 3) * (H_ / 4) + tid] = v3;
}

// ---------------------------------------------------------------------------
extern "C" void kernel_launch(void* const* d_in, const int* in_sizes, int n_in,
                              void* d_out, int out_size) {
    const int*   ids  = (const int*)  d_in[0];
    const float* X    = (const float*)d_in[1];
    const float* msk  = (const float*)d_in[2];
    const float* we   = (const float*)d_in[3];
    const float* W1   = (const float*)d_in[4];
    const float* b1   = (const float*)d_in[5];
    const float* W2   = (const float*)d_in[6];
    const float* b2   = (const float*)d_in[7];
    float* out = (float*)d_out;

    cudaFuncSetAttribute(k1_mma, cudaFuncAttributeMaxDynamicSharedMemorySize, SMEM1);
    cudaFuncSetAttribute(k2_mma, cudaFuncAttributeMaxDynamicSharedMemorySize, SMEM2);

    kw_split<<<dim3(32, 24), dim3(32, 8)>>>(W2);
    k1_mma<<<dim3(8, 8), 128, SMEM1>>>(X, W1, b1);
    k2_mma<<<dim3(8, 6), 128, SMEM2>>>(b2);
    k3_fuse<<<4096, 192>>>(ids, msk, we, out);
}

// round 10
// speedup vs baseline: 2.1430x; 2.1430x over previous
#include <cuda_runtime.h>
#include <cuda_bf16.h>
#include <cstdint>

#define B_   32
#define S_   512
#define E_   8
#define H_   768
#define KG_  100
#define MH_  1000
#define NROW 256
#define MHP  1024            /* padded hidden */
#define K1P  128             /* k1 K padded  */
#define KP1E 136             /* k1 smem pitch (elements), 272B: conflict-free */
#define KP2E 264             /* k2 smem pitch (elements), 528B: conflict-free */

// Scratch (device globals — no allocation allowed)
__device__ __align__(16) __nv_bfloat16 g_Xh[NROW * K1P];
__device__ __align__(16) __nv_bfloat16 g_Xl[NROW * K1P];
__device__ __align__(16) __nv_bfloat16 g_W1h[MHP * K1P];   // [n][k]
__device__ __align__(16) __nv_bfloat16 g_W1l[MHP * K1P];
__device__ __align__(16) __nv_bfloat16 g_W2h[H_ * MHP];    // [n][k]
__device__ __align__(16) __nv_bfloat16 g_W2l[H_ * MHP];
__device__ __align__(16) __nv_bfloat16 g_Hs_hi[NROW * MHP];
__device__ __align__(16) __nv_bfloat16 g_Hs_lo[NROW * MHP];
__device__ __align__(16) float g_ENT2[2][NROW * H_];

// ---------------- helpers ---------------------------------------------------
__device__ __forceinline__ uint32_t smem_u32(const void* p) {
    uint32_t a;
    asm("{ .reg .u64 t; cvta.to.shared.u64 t, %1; cvt.u32.u64 %0, t; }"
        : "=r"(a) : "l"(p));
    return a;
}
__device__ __forceinline__ void splitbf(float x, unsigned short& h,
                                        unsigned short& l) {
    __nv_bfloat16 hb = __float2bfloat16(x);
    float r = x - __bfloat162float(hb);
    __nv_bfloat16 lb = __float2bfloat16(r);
    h = *(unsigned short*)&hb;
    l = *(unsigned short*)&lb;
}
__device__ __forceinline__ void ldm_x4(uint32_t* r, uint32_t addr) {
    asm volatile("ldmatrix.sync.aligned.m8n8.x4.shared.b16 {%0,%1,%2,%3}, [%4];"
                 : "=r"(r[0]), "=r"(r[1]), "=r"(r[2]), "=r"(r[3]) : "r"(addr));
}
__device__ __forceinline__ void ldm_x2(uint32_t* r, uint32_t addr) {
    asm volatile("ldmatrix.sync.aligned.m8n8.x2.shared.b16 {%0,%1}, [%2];"
                 : "=r"(r[0]), "=r"(r[1]) : "r"(addr));
}
__device__ __forceinline__ void mma16816(float* c, const uint32_t* a,
                                         const uint32_t* b) {
    asm volatile(
        "mma.sync.aligned.m16n8k16.row.col.f32.bf16.bf16.f32 "
        "{%0,%1,%2,%3}, {%4,%5,%6,%7}, {%8,%9}, {%0,%1,%2,%3};"
        : "+f"(c[0]), "+f"(c[1]), "+f"(c[2]), "+f"(c[3])
        : "r"(a[0]), "r"(a[1]), "r"(a[2]), "r"(a[3]), "r"(b[0]), "r"(b[1]));
}

// ---------------------------------------------------------------------------
// kprep: split EVERYTHING once.
//   bid <  768 : W2 32x32 transpose tile -> g_W2h/l [n][k=1024pad]
//   bid <  896 : W1 32x32 transpose tile -> g_W1h/l [n=1024pad][k=128pad]
//   bid <  928 : X  32x32 tile (no transpose) -> g_Xh/l [256][128pad]
// block (32, 8)
// ---------------------------------------------------------------------------
__global__ void __launch_bounds__(256) kprep(const float* __restrict__ W2,
                                             const float* __restrict__ W1,
                                             const float* __restrict__ X) {
    __shared__ unsigned short sh[32][33], sl[32][33];
    const int bid = blockIdx.x;
    const int tx = threadIdx.x, ty = threadIdx.y;

    if (bid < 768) {
        const int k0 = (bid & 31) * 32, n0 = (bid >> 5) * 32;
        #pragma unroll
        for (int j = 0; j < 4; j++) {
            int k = k0 + ty + j * 8;
            float v = (k < MH_) ? __ldg(W2 + (long long)k * H_ + n0 + tx) : 0.0f;
            unsigned short h, l; splitbf(v, h, l);
            sh[ty + j * 8][tx] = h; sl[ty + j * 8][tx] = l;
        }
        __syncthreads();
        #pragma unroll
        for (int j = 0; j < 4; j++) {
            int nn = ty + j * 8;
            g_W2h[(n0 + nn) * MHP + k0 + tx] = *(__nv_bfloat16*)&sh[tx][nn];
            g_W2l[(n0 + nn) * MHP + k0 + tx] = *(__nv_bfloat16*)&sl[tx][nn];
        }
    } else if (bid < 896) {
        const int t = bid - 768;
        const int k0 = (t & 3) * 32, n0 = (t >> 2) * 32;
        #pragma unroll
        for (int j = 0; j < 4; j++) {
            int k = k0 + ty + j * 8;
            float v = (k < KG_ && (n0 + tx) < MH_) ? __ldg(W1 + k * MH_ + n0 + tx)
                                                   : 0.0f;
            unsigned short h, l; splitbf(v, h, l);
            sh[ty + j * 8][tx] = h; sl[ty + j * 8][tx] = l;
        }
        __syncthreads();
        #pragma unroll
        for (int j = 0; j < 4; j++) {
            int nn = ty + j * 8;
            g_W1h[(n0 + nn) * K1P + k0 + tx] = *(__nv_bfloat16*)&sh[tx][nn];
            g_W1l[(n0 + nn) * K1P + k0 + tx] = *(__nv_bfloat16*)&sl[tx][nn];
        }
    } else {
        const int t = bid - 896;
        const int r0 = (t >> 2) * 32, k0 = (t & 3) * 32;
        #pragma unroll
        for (int j = 0; j < 4; j++) {
            int r = r0 + ty + j * 8, k = k0 + tx;
            float v = (k < KG_) ? __ldg(X + r * KG_ + k) : 0.0f;
            unsigned short h, l; splitbf(v, h, l);
            g_Xh[r * K1P + k] = *(__nv_bfloat16*)&h;
            g_Xl[r * K1P + k] = *(__nv_bfloat16*)&l;
        }
    }
}

// ---------------------------------------------------------------------------
// K1 (HMMA): Hs = relu(X @ W1 + b1) -> pre-split bf16 hi/lo [256][1024]
// grid (8, 8): M tile 32, N tile 128. block 128 (4 warps, N-slice 32 each).
// K = 128 (8 k16 steps). Pure uint4 staging of pre-split operands.
// ---------------------------------------------------------------------------
#define SM1_AL (32 * KP1E * 2)            /* 8704  */
#define SM1_BH (2 * SM1_AL)               /* 17408 */
#define SM1_BL (SM1_BH + 128 * KP1E * 2)  /* 52224 */
#define SMEM1  (SM1_BL + 128 * KP1E * 2)  /* 87040 */

__global__ void __launch_bounds__(128) k1_mma(const float* __restrict__ b1) {
    extern __shared__ char dsm[];
    const uint32_t sb = smem_u32(dsm);
    const int tid = threadIdx.x;
    const int lane = tid & 31, wid = tid >> 5;
    const int rb = blockIdx.x * 32;
    const int n0 = blockIdx.y * 128;

    // Stage A (hi/lo): 32 rows x 16 uint4 each
    #pragma unroll
    for (int i = 0; i < 4; i++) {
        int idx = tid + i * 128;                 // 512 total
        int r = idx >> 4, c = idx & 15;
        uint4 vh = *(const uint4*)(g_Xh + (rb + r) * K1P + c * 8);
        uint4 vl = *(const uint4*)(g_Xl + (rb + r) * K1P + c * 8);
        *(uint4*)(dsm + (r * KP1E + c * 8) * 2)          = vh;
        *(uint4*)(dsm + SM1_AL + (r * KP1E + c * 8) * 2) = vl;
    }
    // Stage B (hi/lo): 128 rows x 16 uint4 each
    #pragma unroll
    for (int i = 0; i < 16; i++) {
        int idx = tid + i * 128;                 // 2048 total
        int n = idx >> 4, c = idx & 15;
        uint4 vh = *(const uint4*)(g_W1h + (n0 + n) * K1P + c * 8);
        uint4 vl = *(const uint4*)(g_W1l + (n0 + n) * K1P + c * 8);
        *(uint4*)(dsm + SM1_BH + (n * KP1E + c * 8) * 2) = vh;
        *(uint4*)(dsm + SM1_BL + (n * KP1E + c * 8) * 2) = vl;
    }
    __syncthreads();

    const int n_w = wid * 32;
    float acc[2][4][4];
    #pragma unroll
    for (int i = 0; i < 2; i++)
        #pragma unroll
        for (int j = 0; j < 4; j++)
            #pragma unroll
            for (int q = 0; q < 4; q++) acc[i][j][q] = 0.0f;

    const uint32_t arow = lane & 15;
    const uint32_t akof = (lane >> 4) << 3;
    const uint32_t brow = lane & 7;
    const uint32_t bkof = ((lane >> 3) & 1) << 3;

    #pragma unroll
    for (int ks = 0; ks < 8; ks++) {
        const uint32_t kk = ks * 16;
        uint32_t ah[2][4], al[2][4], bh[4][2], bl[4][2];
        #pragma unroll
        for (int i = 0; i < 2; i++) {
            uint32_t ro = (i * 16 + arow) * KP1E + kk + akof;
            ldm_x4(ah[i], sb + ro * 2);
            ldm_x4(al[i], sb + SM1_AL + ro * 2);
        }
        #pragma unroll
        for (int j = 0; j < 4; j++) {
            uint32_t ro = (n_w + j * 8 + brow) * KP1E + kk + bkof;
            ldm_x2(bh[j], sb + SM1_BH + ro * 2);
            ldm_x2(bl[j], sb + SM1_BL + ro * 2);
        }
        #pragma unroll
        for (int i = 0; i < 2; i++)
            #pragma unroll
            for (int j = 0; j < 4; j++) {
                mma16816(acc[i][j], ah[i], bh[j]);
                mma16816(acc[i][j], ah[i], bl[j]);
                mma16816(acc[i][j], al[i], bh[j]);
            }
    }

    // Epilogue: +b1, relu, split, store hi/lo (pad cols >= MH_ -> 0)
    #pragma unroll
    for (int i = 0; i < 2; i++) {
        int row = rb + i * 16 + (lane >> 2);
        #pragma unroll
        for (int j = 0; j < 4; j++) {
            int col = n0 + n_w + j * 8 + (lane & 3) * 2;
            float bb0 = (col     < MH_) ? __ldg(b1 + col)     : 0.0f;
            float bb1 = (col + 1 < MH_) ? __ldg(b1 + col + 1) : 0.0f;
            float f0 = fmaxf(acc[i][j][0] + bb0, 0.0f);
            float f1 = fmaxf(acc[i][j][1] + bb1, 0.0f);
            float f2 = fmaxf(acc[i][j][2] + bb0, 0.0f);
            float f3 = fmaxf(acc[i][j][3] + bb1, 0.0f);
            if (col >= MH_) f0 = f1 = f2 = f3 = 0.0f;
            unsigned short h0, l0, h1, l1;
            splitbf(f0, h0, l0); splitbf(f1, h1, l1);
            *(uint32_t*)(g_Hs_hi + row * MHP + col) = (uint32_t)h0 | ((uint32_t)h1 << 16);
            *(uint32_t*)(g_Hs_lo + row * MHP + col) = (uint32_t)l0 | ((uint32_t)l1 << 16);
            splitbf(f2, h0, l0); splitbf(f3, h1, l1);
            *(uint32_t*)(g_Hs_hi + (row + 8) * MHP + col) = (uint32_t)h0 | ((uint32_t)h1 << 16);
            *(uint32_t*)(g_Hs_lo + (row + 8) * MHP + col) = (uint32_t)l0 | ((uint32_t)l1 << 16);
        }
    }
}

// ---------------------------------------------------------------------------
// K2 (HMMA): ENT_part[kz] = Hs @ W2T (+ b2 on kz==0)
// grid (8, 12, 2): M tile 32, N tile 64, K-split 2 (512 each, 2x256 chunks).
// block 128 (4 warps, N-slice 16 each).
// ---------------------------------------------------------------------------
#define SM2_AL (32 * KP2E * 2)            /* 16896  */
#define SM2_BH (2 * SM2_AL)               /* 33792  */
#define SM2_BL (SM2_BH + 64 * KP2E * 2)   /* 67584  */
#define SMEM2  (SM2_BL + 64 * KP2E * 2)   /* 101376 */

__global__ void __launch_bounds__(128) k2_mma(const float* __restrict__ b2) {
    extern __shared__ char dsm[];
    const uint32_t sb = smem_u32(dsm);
    const int tid = threadIdx.x;
    const int lane = tid & 31, wid = tid >> 5;
    const int rb = blockIdx.x * 32;
    const int n0 = blockIdx.y * 64;
    const int kz = blockIdx.z;
    const int n_w = wid * 16;

    float acc[2][2][4];
    #pragma unroll
    for (int i = 0; i < 2; i++)
        #pragma unroll
        for (int j = 0; j < 2; j++)
            #pragma unroll
            for (int q = 0; q < 4; q++) acc[i][j][q] = 0.0f;

    const uint32_t arow = lane & 15;
    const uint32_t akof = (lane >> 4) << 3;
    const uint32_t brow = lane & 7;
    const uint32_t bkof = ((lane >> 3) & 1) << 3;

    #pragma unroll
    for (int ch = 0; ch < 2; ch++) {
        const int kb = kz * 512 + ch * 256;
        if (ch) __syncthreads();

        // Stage A (hi/lo): 32 rows x 32 uint4
        #pragma unroll
        for (int i = 0; i < 8; i++) {
            int idx = tid + i * 128;              // 1024
            int r = idx >> 5, c = idx & 31;
            uint4 vh = *(const uint4*)(g_Hs_hi + (rb + r) * MHP + kb + c * 8);
            uint4 vl = *(const uint4*)(g_Hs_lo + (rb + r) * MHP + kb + c * 8);
            *(uint4*)(dsm + (r * KP2E + c * 8) * 2)          = vh;
            *(uint4*)(dsm + SM2_AL + (r * KP2E + c * 8) * 2) = vl;
        }
        // Stage B (hi/lo): 64 rows x 32 uint4
        #pragma unroll
        for (int i = 0; i < 16; i++) {
            int idx = tid + i * 128;              // 2048
            int n = idx >> 5, c = idx & 31;
            uint4 vh = *(const uint4*)(g_W2h + (n0 + n) * MHP + kb + c * 8);
            uint4 vl = *(const uint4*)(g_W2l + (n0 + n) * MHP + kb + c * 8);
            *(uint4*)(dsm + SM2_BH + (n * KP2E + c * 8) * 2) = vh;
            *(uint4*)(dsm + SM2_BL + (n * KP2E + c * 8) * 2) = vl;
        }
        __syncthreads();

        #pragma unroll 4
        for (int ks = 0; ks < 16; ks++) {
            const uint32_t kk = ks * 16;
            uint32_t ah[2][4], al[2][4], bh[2][2], bl[2][2];
            #pragma unroll
            for (int i = 0; i < 2; i++) {
                uint32_t ro = (i * 16 + arow) * KP2E + kk + akof;
                ldm_x4(ah[i], sb + ro * 2);
                ldm_x4(al[i], sb + SM2_AL + ro * 2);
            }
            #pragma unroll
            for (int j = 0; j < 2; j++) {
                uint32_t ro = (n_w + j * 8 + brow) * KP2E + kk + bkof;
                ldm_x2(bh[j], sb + SM2_BH + ro * 2);
                ldm_x2(bl[j], sb + SM2_BL + ro * 2);
            }
            #pragma unroll
            for (int i = 0; i < 2; i++)
                #pragma unroll
                for (int j = 0; j < 2; j++) {
                    mma16816(acc[i][j], ah[i], bh[j]);
                    mma16816(acc[i][j], ah[i], bl[j]);
                    mma16816(acc[i][j], al[i], bh[j]);
                }
        }
    }

    // Epilogue: +b2 (kz==0 only), store fp32 partial
    float* dst = g_ENT2[kz];
    #pragma unroll
    for (int i = 0; i < 2; i++) {
        int row = rb + i * 16 + (lane >> 2);
        #pragma unroll
        for (int j = 0; j < 2; j++) {
            int col = n0 + n_w + j * 8 + (lane & 3) * 2;
            float bb0 = 0.f, bb1 = 0.f;
            if (kz == 0) { bb0 = __ldg(b2 + col); bb1 = __ldg(b2 + col + 1); }
            float2 o0 = make_float2(acc[i][j][0] + bb0, acc[i][j][1] + bb1);
            float2 o1 = make_float2(acc[i][j][2] + bb0, acc[i][j][3] + bb1);
            *(float2*)(dst + row * H_ + col)       = o0;
            *(float2*)(dst + (row + 8) * H_ + col) = o1;
        }
    }
}

// ---------------------------------------------------------------------------
// K3: out = gather + masked entity add; sums the 2 ENT partials inline.
// 4 rows per block -> 4096 blocks x 192 threads.
// ---------------------------------------------------------------------------
__global__ void __launch_bounds__(192) k3_fuse(const int*   __restrict__ ids,
                                               const float* __restrict__ mask,
                                               const float* __restrict__ we,
                                               float*       __restrict__ out) {
    const int rblk = blockIdx.x;          // 4096
    const int b    = rblk >> 7;
    const int s0   = (rblk & 127) << 2;
    const int row0 = b * S_ + s0;
    const int tid  = threadIdx.x;

    __shared__ float    sm[E_][4];
    __shared__ unsigned sflag;

    int wid0 = __ldg(ids + row0 + 0);
    int wid1 = __ldg(ids + row0 + 1);
    int wid2 = __ldg(ids + row0 + 2);
    int wid3 = __ldg(ids + row0 + 3);

    const float4* __restrict__ we4 = (const float4*)we;
    float4 v0 = we4[(long long)wid0 * (H_ / 4) + tid];
    float4 v1 = we4[(long long)wid1 * (H_ / 4) + tid];
    float4 v2 = we4[(long long)wid2 * (H_ / 4) + tid];
    float4 v3 = we4[(long long)wid3 * (H_ / 4) + tid];

    if (tid < 32) {
        int e  = tid >> 2;
        int rr = tid & 3;
        float m = __ldg(mask + (b * E_ + e) * S_ + s0 + rr);
        sm[e][rr] = m;
        unsigned bal = __ballot_sync(0xffffffffu, m != 0.0f);
        if (tid == 0) sflag = bal;
    }
    __syncthreads();

    const unsigned flag = sflag;
    if (flag) {
        #pragma unroll
        for (int e = 0; e < E_; e++) {
            unsigned f4 = (flag >> (e * 4)) & 0xFu;
            if (f4) {
                const int idx = (b * E_ + e) * (H_ / 4) + tid;
                float4 p  = ((const float4*)g_ENT2[0])[idx];
                float4 p1 = ((const float4*)g_ENT2[1])[idx];
                p.x += p1.x; p.y += p1.y; p.z += p1.z; p.w += p1.w;
                if (f4 & 1u) { float m = sm[e][0];
                    v0.x = fmaf(m, p.x, v0.x); v0.y = fmaf(m, p.y, v0.y);
                    v0.z = fmaf(m, p.z, v0.z); v0.w = fmaf(m, p.w, v0.w); }
                if (f4 & 2u) { float m = sm[e][1];
                    v1.x = fmaf(m, p.x, v1.x); v1.y = fmaf(m, p.y, v1.y);
                    v1.z = fmaf(m, p.z, v1.z); v1.w = fmaf(m, p.w, v1.w); }
                if (f4 & 4u) { float m = sm[e][2];
                    v2.x = fmaf(m, p.x, v2.x); v2.y = fmaf(m, p.y, v2.y);
                    v2.z = fmaf(m, p.z, v2.z); v2.w = fmaf(m, p.w, v2.w); }
                if (f4 & 8u) { float m = sm[e][3];
                    v3.x = fmaf(m, p.x, v3.x); v3.y = fmaf(m, p.y, v3.y);
                    v3.z = fmaf(m, p.z, v3.z); v3.w = fmaf(m, p.w, v3.w); }
            }
        }
    }

    float4* __restrict__ out4 = (float4*)out;
    out4[(long long)(row0 + 0) * (H_ / 4) + tid] = v0;
    out4[(long long)(row0 + 1) * (H_ / 4) + tid] = v1;
    out4[(long long)(row0 + 2) * (H_ / 4) + tid] = v2;
    out4[(long long)(row0 + 3) * (H_ / 4) + tid] = v3;
}

// ---------------------------------------------------------------------------
extern "C" void kernel_launch(void* const* d_in, const int* in_sizes, int n_in,
                              void* d_out, int out_size) {
    const int*   ids  = (const int*)  d_in[0];
    const float* X    = (const float*)d_in[1];
    const float* msk  = (const float*)d_in[2];
    const float* we   = (const float*)d_in[3];
    const float* W1   = (const float*)d_in[4];
    const float* b1   = (const float*)d_in[5];
    const float* W2   = (const float*)d_in[6];
    const float* b2   = (const float*)d_in[7];
    float* out = (float*)d_out;

    cudaFuncSetAttribute(k1_mma, cudaFuncAttributeMaxDynamicSharedMemorySize, SMEM1);
    cudaFuncSetAttribute(k2_mma, cudaFuncAttributeMaxDynamicSharedMemorySize, SMEM2);

    kprep<<<928, dim3(32, 8)>>>(W2, W1, X);
    k1_mma<<<dim3(8, 8), 128, SMEM1>>>(b1);
    k2_mma<<<dim3(8, 12, 2), 128, SMEM2>>>(b2);
    k3_fuse<<<4096, 192>>>(ids, msk, we, out);
}

// round 11
// speedup vs baseline: 2.4193x; 1.1289x over previous
#include <cuda_runtime.h>
#include <cuda_bf16.h>
#include <cstdint>

#define B_   32
#define S_   512
#define E_   8
#define H_   768
#define KG_  100
#define MH_  1000
#define NROW 256
#define MHP  1024            /* padded hidden */
#define K1P  128             /* k1 K padded  */
#define KP1E 136             /* k1 smem pitch (elements), 272B: conflict-free */
#define KP2E 264             /* k2 smem pitch (elements), 528B: conflict-free */

// Scratch (device globals — no allocation allowed)
__device__ __align__(16) __nv_bfloat16 g_Xh[NROW * K1P];
__device__ __align__(16) __nv_bfloat16 g_Xl[NROW * K1P];
__device__ __align__(16) __nv_bfloat16 g_W1h[MHP * K1P];   // [n][k]
__device__ __align__(16) __nv_bfloat16 g_W1l[MHP * K1P];
__device__ __align__(16) __nv_bfloat16 g_W2h[H_ * MHP];    // [n][k]
__device__ __align__(16) __nv_bfloat16 g_W2l[H_ * MHP];
__device__ __align__(16) __nv_bfloat16 g_Hs_hi[NROW * MHP];
__device__ __align__(16) __nv_bfloat16 g_Hs_lo[NROW * MHP];
__device__ __align__(16) float g_ENT2[2][NROW * H_];

// ---------------- helpers ---------------------------------------------------
__device__ __forceinline__ uint32_t smem_u32(const void* p) {
    uint32_t a;
    asm("{ .reg .u64 t; cvta.to.shared.u64 t, %1; cvt.u32.u64 %0, t; }"
        : "=r"(a) : "l"(p));
    return a;
}
__device__ __forceinline__ void splitbf(float x, unsigned short& h,
                                        unsigned short& l) {
    __nv_bfloat16 hb = __float2bfloat16(x);
    float r = x - __bfloat162float(hb);
    __nv_bfloat16 lb = __float2bfloat16(r);
    h = *(unsigned short*)&hb;
    l = *(unsigned short*)&lb;
}
__device__ __forceinline__ void ldm_x4(uint32_t* r, uint32_t addr) {
    asm volatile("ldmatrix.sync.aligned.m8n8.x4.shared.b16 {%0,%1,%2,%3}, [%4];"
                 : "=r"(r[0]), "=r"(r[1]), "=r"(r[2]), "=r"(r[3]) : "r"(addr));
}
__device__ __forceinline__ void ldm_x2(uint32_t* r, uint32_t addr) {
    asm volatile("ldmatrix.sync.aligned.m8n8.x2.shared.b16 {%0,%1}, [%2];"
                 : "=r"(r[0]), "=r"(r[1]) : "r"(addr));
}
__device__ __forceinline__ void mma16816(float* c, const uint32_t* a,
                                         const uint32_t* b) {
    asm volatile(
        "mma.sync.aligned.m16n8k16.row.col.f32.bf16.bf16.f32 "
        "{%0,%1,%2,%3}, {%4,%5,%6,%7}, {%8,%9}, {%0,%1,%2,%3};"
        : "+f"(c[0]), "+f"(c[1]), "+f"(c[2]), "+f"(c[3])
        : "r"(a[0]), "r"(a[1]), "r"(a[2]), "r"(a[3]), "r"(b[0]), "r"(b[1]));
}

// ---------------------------------------------------------------------------
// kprep: split EVERYTHING once.  (unchanged, passing)
// ---------------------------------------------------------------------------
__global__ void __launch_bounds__(256) kprep(const float* __restrict__ W2,
                                             const float* __restrict__ W1,
                                             const float* __restrict__ X) {
    __shared__ unsigned short sh[32][33], sl[32][33];
    const int bid = blockIdx.x;
    const int tx = threadIdx.x, ty = threadIdx.y;

    if (bid < 768) {
        const int k0 = (bid & 31) * 32, n0 = (bid >> 5) * 32;
        #pragma unroll
        for (int j = 0; j < 4; j++) {
            int k = k0 + ty + j * 8;
            float v = (k < MH_) ? __ldg(W2 + (long long)k * H_ + n0 + tx) : 0.0f;
            unsigned short h, l; splitbf(v, h, l);
            sh[ty + j * 8][tx] = h; sl[ty + j * 8][tx] = l;
        }
        __syncthreads();
        #pragma unroll
        for (int j = 0; j < 4; j++) {
            int nn = ty + j * 8;
            g_W2h[(n0 + nn) * MHP + k0 + tx] = *(__nv_bfloat16*)&sh[tx][nn];
            g_W2l[(n0 + nn) * MHP + k0 + tx] = *(__nv_bfloat16*)&sl[tx][nn];
        }
    } else if (bid < 896) {
        const int t = bid - 768;
        const int k0 = (t & 3) * 32, n0 = (t >> 2) * 32;
        #pragma unroll
        for (int j = 0; j < 4; j++) {
            int k = k0 + ty + j * 8;
            float v = (k < KG_ && (n0 + tx) < MH_) ? __ldg(W1 + k * MH_ + n0 + tx)
                                                   : 0.0f;
            unsigned short h, l; splitbf(v, h, l);
            sh[ty + j * 8][tx] = h; sl[ty + j * 8][tx] = l;
        }
        __syncthreads();
        #pragma unroll
        for (int j = 0; j < 4; j++) {
            int nn = ty + j * 8;
            g_W1h[(n0 + nn) * K1P + k0 + tx] = *(__nv_bfloat16*)&sh[tx][nn];
            g_W1l[(n0 + nn) * K1P + k0 + tx] = *(__nv_bfloat16*)&sl[tx][nn];
        }
    } else {
        const int t = bid - 896;
        const int r0 = (t >> 2) * 32, k0 = (t & 3) * 32;
        #pragma unroll
        for (int j = 0; j < 4; j++) {
            int r = r0 + ty + j * 8, k = k0 + tx;
            float v = (k < KG_) ? __ldg(X + r * KG_ + k) : 0.0f;
            unsigned short h, l; splitbf(v, h, l);
            g_Xh[r * K1P + k] = *(__nv_bfloat16*)&h;
            g_Xl[r * K1P + k] = *(__nv_bfloat16*)&l;
        }
    }
}

// ---------------------------------------------------------------------------
// K1 (HMMA): unchanged, passing.
// ---------------------------------------------------------------------------
#define SM1_AL (32 * KP1E * 2)
#define SM1_BH (2 * SM1_AL)
#define SM1_BL (SM1_BH + 128 * KP1E * 2)
#define SMEM1  (SM1_BL + 128 * KP1E * 2)

__global__ void __launch_bounds__(128) k1_mma(const float* __restrict__ b1) {
    extern __shared__ char dsm[];
    const uint32_t sb = smem_u32(dsm);
    const int tid = threadIdx.x;
    const int lane = tid & 31, wid = tid >> 5;
    const int rb = blockIdx.x * 32;
    const int n0 = blockIdx.y * 128;

    #pragma unroll
    for (int i = 0; i < 4; i++) {
        int idx = tid + i * 128;
        int r = idx >> 4, c = idx & 15;
        uint4 vh = *(const uint4*)(g_Xh + (rb + r) * K1P + c * 8);
        uint4 vl = *(const uint4*)(g_Xl + (rb + r) * K1P + c * 8);
        *(uint4*)(dsm + (r * KP1E + c * 8) * 2)          = vh;
        *(uint4*)(dsm + SM1_AL + (r * KP1E + c * 8) * 2) = vl;
    }
    #pragma unroll
    for (int i = 0; i < 16; i++) {
        int idx = tid + i * 128;
        int n = idx >> 4, c = idx & 15;
        uint4 vh = *(const uint4*)(g_W1h + (n0 + n) * K1P + c * 8);
        uint4 vl = *(const uint4*)(g_W1l + (n0 + n) * K1P + c * 8);
        *(uint4*)(dsm + SM1_BH + (n * KP1E + c * 8) * 2) = vh;
        *(uint4*)(dsm + SM1_BL + (n * KP1E + c * 8) * 2) = vl;
    }
    __syncthreads();

    const int n_w = wid * 32;
    float acc[2][4][4];
    #pragma unroll
    for (int i = 0; i < 2; i++)
        #pragma unroll
        for (int j = 0; j < 4; j++)
            #pragma unroll
            for (int q = 0; q < 4; q++) acc[i][j][q] = 0.0f;

    const uint32_t arow = lane & 15;
    const uint32_t akof = (lane >> 4) << 3;
    const uint32_t brow = lane & 7;
    const uint32_t bkof = ((lane >> 3) & 1) << 3;

    #pragma unroll
    for (int ks = 0; ks < 8; ks++) {
        const uint32_t kk = ks * 16;
        uint32_t ah[2][4], al[2][4], bh[4][2], bl[4][2];
        #pragma unroll
        for (int i = 0; i < 2; i++) {
            uint32_t ro = (i * 16 + arow) * KP1E + kk + akof;
            ldm_x4(ah[i], sb + ro * 2);
            ldm_x4(al[i], sb + SM1_AL + ro * 2);
        }
        #pragma unroll
        for (int j = 0; j < 4; j++) {
            uint32_t ro = (n_w + j * 8 + brow) * KP1E + kk + bkof;
            ldm_x2(bh[j], sb + SM1_BH + ro * 2);
            ldm_x2(bl[j], sb + SM1_BL + ro * 2);
        }
        #pragma unroll
        for (int i = 0; i < 2; i++)
            #pragma unroll
            for (int j = 0; j < 4; j++) {
                mma16816(acc[i][j], ah[i], bh[j]);
                mma16816(acc[i][j], ah[i], bl[j]);
                mma16816(acc[i][j], al[i], bh[j]);
            }
    }

    #pragma unroll
    for (int i = 0; i < 2; i++) {
        int row = rb + i * 16 + (lane >> 2);
        #pragma unroll
        for (int j = 0; j < 4; j++) {
            int col = n0 + n_w + j * 8 + (lane & 3) * 2;
            float bb0 = (col     < MH_) ? __ldg(b1 + col)     : 0.0f;
            float bb1 = (col + 1 < MH_) ? __ldg(b1 + col + 1) : 0.0f;
            float f0 = fmaxf(acc[i][j][0] + bb0, 0.0f);
            float f1 = fmaxf(acc[i][j][1] + bb1, 0.0f);
            float f2 = fmaxf(acc[i][j][2] + bb0, 0.0f);
            float f3 = fmaxf(acc[i][j][3] + bb1, 0.0f);
            if (col >= MH_) f0 = f1 = f2 = f3 = 0.0f;
            unsigned short h0, l0, h1, l1;
            splitbf(f0, h0, l0); splitbf(f1, h1, l1);
            *(uint32_t*)(g_Hs_hi + row * MHP + col) = (uint32_t)h0 | ((uint32_t)h1 << 16);
            *(uint32_t*)(g_Hs_lo + row * MHP + col) = (uint32_t)l0 | ((uint32_t)l1 << 16);
            splitbf(f2, h0, l0); splitbf(f3, h1, l1);
            *(uint32_t*)(g_Hs_hi + (row + 8) * MHP + col) = (uint32_t)h0 | ((uint32_t)h1 << 16);
            *(uint32_t*)(g_Hs_lo + (row + 8) * MHP + col) = (uint32_t)l0 | ((uint32_t)l1 << 16);
        }
    }
}

// ---------------------------------------------------------------------------
// K2 (HMMA): unchanged, passing.
// ---------------------------------------------------------------------------
#define SM2_AL (32 * KP2E * 2)
#define SM2_BH (2 * SM2_AL)
#define SM2_BL (SM2_BH + 64 * KP2E * 2)
#define SMEM2  (SM2_BL + 64 * KP2E * 2)

__global__ void __launch_bounds__(128) k2_mma(const float* __restrict__ b2) {
    extern __shared__ char dsm[];
    const uint32_t sb = smem_u32(dsm);
    const int tid = threadIdx.x;
    const int lane = tid & 31, wid = tid >> 5;
    const int rb = blockIdx.x * 32;
    const int n0 = blockIdx.y * 64;
    const int kz = blockIdx.z;
    const int n_w = wid * 16;

    float acc[2][2][4];
    #pragma unroll
    for (int i = 0; i < 2; i++)
        #pragma unroll
        for (int j = 0; j < 2; j++)
            #pragma unroll
            for (int q = 0; q < 4; q++) acc[i][j][q] = 0.0f;

    const uint32_t arow = lane & 15;
    const uint32_t akof = (lane >> 4) << 3;
    const uint32_t brow = lane & 7;
    const uint32_t bkof = ((lane >> 3) & 1) << 3;

    #pragma unroll
    for (int ch = 0; ch < 2; ch++) {
        const int kb = kz * 512 + ch * 256;
        if (ch) __syncthreads();

        #pragma unroll
        for (int i = 0; i < 8; i++) {
            int idx = tid + i * 128;
            int r = idx >> 5, c = idx & 31;
            uint4 vh = *(const uint4*)(g_Hs_hi + (rb + r) * MHP + kb + c * 8);
            uint4 vl = *(const uint4*)(g_Hs_lo + (rb + r) * MHP + kb + c * 8);
            *(uint4*)(dsm + (r * KP2E + c * 8) * 2)          = vh;
            *(uint4*)(dsm + SM2_AL + (r * KP2E + c * 8) * 2) = vl;
        }
        #pragma unroll
        for (int i = 0; i < 16; i++) {
            int idx = tid + i * 128;
            int n = idx >> 5, c = idx & 31;
            uint4 vh = *(const uint4*)(g_W2h + (n0 + n) * MHP + kb + c * 8);
            uint4 vl = *(const uint4*)(g_W2l + (n0 + n) * MHP + kb + c * 8);
            *(uint4*)(dsm + SM2_BH + (n * KP2E + c * 8) * 2) = vh;
            *(uint4*)(dsm + SM2_BL + (n * KP2E + c * 8) * 2) = vl;
        }
        __syncthreads();

        #pragma unroll 4
        for (int ks = 0; ks < 16; ks++) {
            const uint32_t kk = ks * 16;
            uint32_t ah[2][4], al[2][4], bh[2][2], bl[2][2];
            #pragma unroll
            for (int i = 0; i < 2; i++) {
                uint32_t ro = (i * 16 + arow) * KP2E + kk + akof;
                ldm_x4(ah[i], sb + ro * 2);
                ldm_x4(al[i], sb + SM2_AL + ro * 2);
            }
            #pragma unroll
            for (int j = 0; j < 2; j++) {
                uint32_t ro = (n_w + j * 8 + brow) * KP2E + kk + bkof;
                ldm_x2(bh[j], sb + SM2_BH + ro * 2);
                ldm_x2(bl[j], sb + SM2_BL + ro * 2);
            }
            #pragma unroll
            for (int i = 0; i < 2; i++)
                #pragma unroll
                for (int j = 0; j < 2; j++) {
                    mma16816(acc[i][j], ah[i], bh[j]);
                    mma16816(acc[i][j], ah[i], bl[j]);
                    mma16816(acc[i][j], al[i], bh[j]);
                }
        }
    }

    float* dst = g_ENT2[kz];
    #pragma unroll
    for (int i = 0; i < 2; i++) {
        int row = rb + i * 16 + (lane >> 2);
        #pragma unroll
        for (int j = 0; j < 2; j++) {
            int col = n0 + n_w + j * 8 + (lane & 3) * 2;
            float bb0 = 0.f, bb1 = 0.f;
            if (kz == 0) { bb0 = __ldg(b2 + col); bb1 = __ldg(b2 + col + 1); }
            float2 o0 = make_float2(acc[i][j][0] + bb0, acc[i][j][1] + bb1);
            float2 o1 = make_float2(acc[i][j][2] + bb0, acc[i][j][3] + bb1);
            *(float2*)(dst + row * H_ + col)       = o0;
            *(float2*)(dst + (row + 8) * H_ + col) = o1;
        }
    }
}

// ---------------------------------------------------------------------------
// K3 v2: per-warp masks (no block barrier) + streaming output stores.
// 4 rows per block -> 4096 blocks x 192 threads. Each warp independently
// loads the 32 mask scalars on its lanes (lane = e*4+rr), ballots, and
// shuffles values -- no smem, no __syncthreads. Output uses __stcs so the
// 50MB write stream evicts first and the 93MB embedding table stays
// L2-resident across graph replays.
// ---------------------------------------------------------------------------
__global__ void __launch_bounds__(192) k3_fuse(const int*   __restrict__ ids,
                                               const float* __restrict__ mask,
                                               const float* __restrict__ we,
                                               float*       __restrict__ out) {
    const int rblk = blockIdx.x;          // 4096
    const int b    = rblk >> 7;
    const int s0   = (rblk & 127) << 2;
    const int row0 = b * S_ + s0;
    const int tid  = threadIdx.x;
    const int lane = tid & 31;

    // Fire the 4 independent row gathers first (MLP=4).
    int wid0 = __ldg(ids + row0 + 0);
    int wid1 = __ldg(ids + row0 + 1);
    int wid2 = __ldg(ids + row0 + 2);
    int wid3 = __ldg(ids + row0 + 3);

    const float4* __restrict__ we4 = (const float4*)we;
    float4 v0 = we4[(long long)wid0 * (H_ / 4) + tid];
    float4 v1 = we4[(long long)wid1 * (H_ / 4) + tid];
    float4 v2 = we4[(long long)wid2 * (H_ / 4) + tid];
    float4 v3 = we4[(long long)wid3 * (H_ / 4) + tid];

    // Per-warp mask handling: lane -> (e = lane>>2, rr = lane&3).
    const int e_ln  = lane >> 2;
    const int rr_ln = lane & 3;
    const float mval = __ldg(mask + (b * E_ + e_ln) * S_ + s0 + rr_ln);
    const unsigned flag = __ballot_sync(0xffffffffu, mval != 0.0f);

    if (flag) {
        #pragma unroll
        for (int e = 0; e < E_; e++) {
            const unsigned f4 = (flag >> (e * 4)) & 0xFu;
            if (f4) {
                const int idx = (b * E_ + e) * (H_ / 4) + tid;
                float4 p  = ((const float4*)g_ENT2[0])[idx];
                float4 p1 = ((const float4*)g_ENT2[1])[idx];
                p.x += p1.x; p.y += p1.y; p.z += p1.z; p.w += p1.w;
                const float m0 = __shfl_sync(0xffffffffu, mval, e * 4 + 0);
                const float m1 = __shfl_sync(0xffffffffu, mval, e * 4 + 1);
                const float m2 = __shfl_sync(0xffffffffu, mval, e * 4 + 2);
                const float m3 = __shfl_sync(0xffffffffu, mval, e * 4 + 3);
                if (f4 & 1u) {
                    v0.x = fmaf(m0, p.x, v0.x); v0.y = fmaf(m0, p.y, v0.y);
                    v0.z = fmaf(m0, p.z, v0.z); v0.w = fmaf(m0, p.w, v0.w); }
                if (f4 & 2u) {
                    v1.x = fmaf(m1, p.x, v1.x); v1.y = fmaf(m1, p.y, v1.y);
                    v1.z = fmaf(m1, p.z, v1.z); v1.w = fmaf(m1, p.w, v1.w); }
                if (f4 & 4u) {
                    v2.x = fmaf(m2, p.x, v2.x); v2.y = fmaf(m2, p.y, v2.y);
                    v2.z = fmaf(m2, p.z, v2.z); v2.w = fmaf(m2, p.w, v2.w); }
                if (f4 & 8u) {
                    v3.x = fmaf(m3, p.x, v3.x); v3.y = fmaf(m3, p.y, v3.y);
                    v3.z = fmaf(m3, p.z, v3.z); v3.w = fmaf(m3, p.w, v3.w); }
            }
        }
    }

    float4* __restrict__ out4 = (float4*)out;
    __stcs(out4 + (long long)(row0 + 0) * (H_ / 4) + tid, v0);
    __stcs(out4 + (long long)(row0 + 1) * (H_ / 4) + tid, v1);
    __stcs(out4 + (long long)(row0 + 2) * (H_ / 4) + tid, v2);
    __stcs(out4 + (long long)(row0 + 3) * (H_ / 4) + tid, v3);
}

// ---------------------------------------------------------------------------
extern "C" void kernel_launch(void* const* d_in, const int* in_sizes, int n_in,
                              void* d_out, int out_size) {
    const int*   ids  = (const int*)  d_in[0];
    const float* X    = (const float*)d_in[1];
    const float* msk  = (const float*)d_in[2];
    const float* we   = (const float*)d_in[3];
    const float* W1   = (const float*)d_in[4];
    const float* b1   = (const float*)d_in[5];
    const float* W2   = (const float*)d_in[6];
    const float* b2   = (const float*)d_in[7];
    float* out = (float*)d_out;

    cudaFuncSetAttribute(k1_mma, cudaFuncAttributeMaxDynamicSharedMemorySize, SMEM1);
    cudaFuncSetAttribute(k2_mma, cudaFuncAttributeMaxDynamicSharedMemorySize, SMEM2);

    kprep<<<928, dim3(32, 8)>>>(W2, W1, X);
    k1_mma<<<dim3(8, 8), 128, SMEM1>>>(b1);
    k2_mma<<<dim3(8, 12, 2), 128, SMEM2>>>(b2);
    k3_fuse<<<4096, 192>>>(ids, msk, we, out);
}

// round 12
// speedup vs baseline: 2.4217x; 1.0010x over previous
#include <cuda_runtime.h>
#include <cuda_bf16.h>
#include <cstdint>

#define B_   32
#define S_   512
#define E_   8
#define H_   768
#define KG_  100
#define MH_  1000
#define NROW 256
#define MHP  1024            /* padded hidden */
#define K1P  128             /* k1 K padded  */
#define KP1E 136             /* k1 smem pitch (elements), 272B: conflict-free */
#define KP2E 264             /* k2 smem pitch (elements), 528B: conflict-free */
#define K3_BLOCKS 1184       /* 148 SMs x 8 resident blocks */

// Scratch (device globals — no allocation allowed)
__device__ __align__(16) __nv_bfloat16 g_Xh[NROW * K1P];
__device__ __align__(16) __nv_bfloat16 g_Xl[NROW * K1P];
__device__ __align__(16) __nv_bfloat16 g_W1h[MHP * K1P];   // [n][k]
__device__ __align__(16) __nv_bfloat16 g_W1l[MHP * K1P];
__device__ __align__(16) __nv_bfloat16 g_W2h[H_ * MHP];    // [n][k]
__device__ __align__(16) __nv_bfloat16 g_W2l[H_ * MHP];
__device__ __align__(16) __nv_bfloat16 g_Hs_hi[NROW * MHP];
__device__ __align__(16) __nv_bfloat16 g_Hs_lo[NROW * MHP];
__device__ __align__(16) float g_ENT2[2][NROW * H_];

// ---------------- helpers ---------------------------------------------------
__device__ __forceinline__ uint32_t smem_u32(const void* p) {
    uint32_t a;
    asm("{ .reg .u64 t; cvta.to.shared.u64 t, %1; cvt.u32.u64 %0, t; }"
        : "=r"(a) : "l"(p));
    return a;
}
__device__ __forceinline__ void splitbf(float x, unsigned short& h,
                                        unsigned short& l) {
    __nv_bfloat16 hb = __float2bfloat16(x);
    float r = x - __bfloat162float(hb);
    __nv_bfloat16 lb = __float2bfloat16(r);
    h = *(unsigned short*)&hb;
    l = *(unsigned short*)&lb;
}
__device__ __forceinline__ void ldm_x4(uint32_t* r, uint32_t addr) {
    asm volatile("ldmatrix.sync.aligned.m8n8.x4.shared.b16 {%0,%1,%2,%3}, [%4];"
                 : "=r"(r[0]), "=r"(r[1]), "=r"(r[2]), "=r"(r[3]) : "r"(addr));
}
__device__ __forceinline__ void ldm_x2(uint32_t* r, uint32_t addr) {
    asm volatile("ldmatrix.sync.aligned.m8n8.x2.shared.b16 {%0,%1}, [%2];"
                 : "=r"(r[0]), "=r"(r[1]) : "r"(addr));
}
__device__ __forceinline__ void mma16816(float* c, const uint32_t* a,
                                         const uint32_t* b) {
    asm volatile(
        "mma.sync.aligned.m16n8k16.row.col.f32.bf16.bf16.f32 "
        "{%0,%1,%2,%3}, {%4,%5,%6,%7}, {%8,%9}, {%0,%1,%2,%3};"
        : "+f"(c[0]), "+f"(c[1]), "+f"(c[2]), "+f"(c[3])
        : "r"(a[0]), "r"(a[1]), "r"(a[2]), "r"(a[3]), "r"(b[0]), "r"(b[1]));
}

// ---------------------------------------------------------------------------
// kprep: split EVERYTHING once.  (unchanged, passing)
// ---------------------------------------------------------------------------
__global__ void __launch_bounds__(256) kprep(const float* __restrict__ W2,
                                             const float* __restrict__ W1,
                                             const float* __restrict__ X) {
    __shared__ unsigned short sh[32][33], sl[32][33];
    const int bid = blockIdx.x;
    const int tx = threadIdx.x, ty = threadIdx.y;

    if (bid < 768) {
        const int k0 = (bid & 31) * 32, n0 = (bid >> 5) * 32;
        #pragma unroll
        for (int j = 0; j < 4; j++) {
            int k = k0 + ty + j * 8;
            float v = (k < MH_) ? __ldg(W2 + (long long)k * H_ + n0 + tx) : 0.0f;
            unsigned short h, l; splitbf(v, h, l);
            sh[ty + j * 8][tx] = h; sl[ty + j * 8][tx] = l;
        }
        __syncthreads();
        #pragma unroll
        for (int j = 0; j < 4; j++) {
            int nn = ty + j * 8;
            g_W2h[(n0 + nn) * MHP + k0 + tx] = *(__nv_bfloat16*)&sh[tx][nn];
            g_W2l[(n0 + nn) * MHP + k0 + tx] = *(__nv_bfloat16*)&sl[tx][nn];
        }
    } else if (bid < 896) {
        const int t = bid - 768;
        const int k0 = (t & 3) * 32, n0 = (t >> 2) * 32;
        #pragma unroll
        for (int j = 0; j < 4; j++) {
            int k = k0 + ty + j * 8;
            float v = (k < KG_ && (n0 + tx) < MH_) ? __ldg(W1 + k * MH_ + n0 + tx)
                                                   : 0.0f;
            unsigned short h, l; splitbf(v, h, l);
            sh[ty + j * 8][tx] = h; sl[ty + j * 8][tx] = l;
        }
        __syncthreads();
        #pragma unroll
        for (int j = 0; j < 4; j++) {
            int nn = ty + j * 8;
            g_W1h[(n0 + nn) * K1P + k0 + tx] = *(__nv_bfloat16*)&sh[tx][nn];
            g_W1l[(n0 + nn) * K1P + k0 + tx] = *(__nv_bfloat16*)&sl[tx][nn];
        }
    } else {
        const int t = bid - 896;
        const int r0 = (t >> 2) * 32, k0 = (t & 3) * 32;
        #pragma unroll
        for (int j = 0; j < 4; j++) {
            int r = r0 + ty + j * 8, k = k0 + tx;
            float v = (k < KG_) ? __ldg(X + r * KG_ + k) : 0.0f;
            unsigned short h, l; splitbf(v, h, l);
            g_Xh[r * K1P + k] = *(__nv_bfloat16*)&h;
            g_Xl[r * K1P + k] = *(__nv_bfloat16*)&l;
        }
    }
}

// ---------------------------------------------------------------------------
// K1 (HMMA): unchanged, passing.
// ---------------------------------------------------------------------------
#define SM1_AL (32 * KP1E * 2)
#define SM1_BH (2 * SM1_AL)
#define SM1_BL (SM1_BH + 128 * KP1E * 2)
#define SMEM1  (SM1_BL + 128 * KP1E * 2)

__global__ void __launch_bounds__(128) k1_mma(const float* __restrict__ b1) {
    extern __shared__ char dsm[];
    const uint32_t sb = smem_u32(dsm);
    const int tid = threadIdx.x;
    const int lane = tid & 31, wid = tid >> 5;
    const int rb = blockIdx.x * 32;
    const int n0 = blockIdx.y * 128;

    #pragma unroll
    for (int i = 0; i < 4; i++) {
        int idx = tid + i * 128;
        int r = idx >> 4, c = idx & 15;
        uint4 vh = *(const uint4*)(g_Xh + (rb + r) * K1P + c * 8);
        uint4 vl = *(const uint4*)(g_Xl + (rb + r) * K1P + c * 8);
        *(uint4*)(dsm + (r * KP1E + c * 8) * 2)          = vh;
        *(uint4*)(dsm + SM1_AL + (r * KP1E + c * 8) * 2) = vl;
    }
    #pragma unroll
    for (int i = 0; i < 16; i++) {
        int idx = tid + i * 128;
        int n = idx >> 4, c = idx & 15;
        uint4 vh = *(const uint4*)(g_W1h + (n0 + n) * K1P + c * 8);
        uint4 vl = *(const uint4*)(g_W1l + (n0 + n) * K1P + c * 8);
        *(uint4*)(dsm + SM1_BH + (n * KP1E + c * 8) * 2) = vh;
        *(uint4*)(dsm + SM1_BL + (n * KP1E + c * 8) * 2) = vl;
    }
    __syncthreads();

    const int n_w = wid * 32;
    float acc[2][4][4];
    #pragma unroll
    for (int i = 0; i < 2; i++)
        #pragma unroll
        for (int j = 0; j < 4; j++)
            #pragma unroll
            for (int q = 0; q < 4; q++) acc[i][j][q] = 0.0f;

    const uint32_t arow = lane & 15;
    const uint32_t akof = (lane >> 4) << 3;
    const uint32_t brow = lane & 7;
    const uint32_t bkof = ((lane >> 3) & 1) << 3;

    #pragma unroll
    for (int ks = 0; ks < 8; ks++) {
        const uint32_t kk = ks * 16;
        uint32_t ah[2][4], al[2][4], bh[4][2], bl[4][2];
        #pragma unroll
        for (int i = 0; i < 2; i++) {
            uint32_t ro = (i * 16 + arow) * KP1E + kk + akof;
            ldm_x4(ah[i], sb + ro * 2);
            ldm_x4(al[i], sb + SM1_AL + ro * 2);
        }
        #pragma unroll
        for (int j = 0; j < 4; j++) {
            uint32_t ro = (n_w + j * 8 + brow) * KP1E + kk + bkof;
            ldm_x2(bh[j], sb + SM1_BH + ro * 2);
            ldm_x2(bl[j], sb + SM1_BL + ro * 2);
        }
        #pragma unroll
        for (int i = 0; i < 2; i++)
            #pragma unroll
            for (int j = 0; j < 4; j++) {
                mma16816(acc[i][j], ah[i], bh[j]);
                mma16816(acc[i][j], ah[i], bl[j]);
                mma16816(acc[i][j], al[i], bh[j]);
            }
    }

    #pragma unroll
    for (int i = 0; i < 2; i++) {
        int row = rb + i * 16 + (lane >> 2);
        #pragma unroll
        for (int j = 0; j < 4; j++) {
            int col = n0 + n_w + j * 8 + (lane & 3) * 2;
            float bb0 = (col     < MH_) ? __ldg(b1 + col)     : 0.0f;
            float bb1 = (col + 1 < MH_) ? __ldg(b1 + col + 1) : 0.0f;
            float f0 = fmaxf(acc[i][j][0] + bb0, 0.0f);
            float f1 = fmaxf(acc[i][j][1] + bb1, 0.0f);
            float f2 = fmaxf(acc[i][j][2] + bb0, 0.0f);
            float f3 = fmaxf(acc[i][j][3] + bb1, 0.0f);
            if (col >= MH_) f0 = f1 = f2 = f3 = 0.0f;
            unsigned short h0, l0, h1, l1;
            splitbf(f0, h0, l0); splitbf(f1, h1, l1);
            *(uint32_t*)(g_Hs_hi + row * MHP + col) = (uint32_t)h0 | ((uint32_t)h1 << 16);
            *(uint32_t*)(g_Hs_lo + row * MHP + col) = (uint32_t)l0 | ((uint32_t)l1 << 16);
            splitbf(f2, h0, l0); splitbf(f3, h1, l1);
            *(uint32_t*)(g_Hs_hi + (row + 8) * MHP + col) = (uint32_t)h0 | ((uint32_t)h1 << 16);
            *(uint32_t*)(g_Hs_lo + (row + 8) * MHP + col) = (uint32_t)l0 | ((uint32_t)l1 << 16);
        }
    }
}

// ---------------------------------------------------------------------------
// K2 (HMMA): M tile 64 (was 32) -> halves W2-tile L2 re-reads.
// grid (4, 12, 2): M64, N64, K-split 2 (512 each, 2x256 chunks).
// block 128 (4 warps, N-slice 16 each; each warp covers all 64 M rows).
// ---------------------------------------------------------------------------
#define SM2_AL (64 * KP2E * 2)            /* 33792  */
#define SM2_BH (2 * SM2_AL)               /* 67584  */
#define SM2_BL (SM2_BH + 64 * KP2E * 2)   /* 101376 */
#define SMEM2  (SM2_BL + 64 * KP2E * 2)   /* 135168 */

__global__ void __launch_bounds__(128) k2_mma(const float* __restrict__ b2) {
    extern __shared__ char dsm[];
    const uint32_t sb = smem_u32(dsm);
    const int tid = threadIdx.x;
    const int lane = tid & 31, wid = tid >> 5;
    const int rb = blockIdx.x * 64;
    const int n0 = blockIdx.y * 64;
    const int kz = blockIdx.z;
    const int n_w = wid * 16;

    float acc[4][2][4];
    #pragma unroll
    for (int i = 0; i < 4; i++)
        #pragma unroll
        for (int j = 0; j < 2; j++)
            #pragma unroll
            for (int q = 0; q < 4; q++) acc[i][j][q] = 0.0f;

    const uint32_t arow = lane & 15;
    const uint32_t akof = (lane >> 4) << 3;
    const uint32_t brow = lane & 7;
    const uint32_t bkof = ((lane >> 3) & 1) << 3;

    #pragma unroll
    for (int ch = 0; ch < 2; ch++) {
        const int kb = kz * 512 + ch * 256;
        if (ch) __syncthreads();

        // Stage A (hi/lo): 64 rows x 32 uint4
        #pragma unroll
        for (int i = 0; i < 16; i++) {
            int idx = tid + i * 128;
            int r = idx >> 5, c = idx & 31;
            uint4 vh = *(const uint4*)(g_Hs_hi + (rb + r) * MHP + kb + c * 8);
            uint4 vl = *(const uint4*)(g_Hs_lo + (rb + r) * MHP + kb + c * 8);
            *(uint4*)(dsm + (r * KP2E + c * 8) * 2)          = vh;
            *(uint4*)(dsm + SM2_AL + (r * KP2E + c * 8) * 2) = vl;
        }
        // Stage B (hi/lo): 64 rows x 32 uint4
        #pragma unroll
        for (int i = 0; i < 16; i++) {
            int idx = tid + i * 128;
            int n = idx >> 5, c = idx & 31;
            uint4 vh = *(const uint4*)(g_W2h + (n0 + n) * MHP + kb + c * 8);
            uint4 vl = *(const uint4*)(g_W2l + (n0 + n) * MHP + kb + c * 8);
            *(uint4*)(dsm + SM2_BH + (n * KP2E + c * 8) * 2) = vh;
            *(uint4*)(dsm + SM2_BL + (n * KP2E + c * 8) * 2) = vl;
        }
        __syncthreads();

        #pragma unroll 2
        for (int ks = 0; ks < 16; ks++) {
            const uint32_t kk = ks * 16;
            uint32_t ah[4][4], al[4][4], bh[2][2], bl[2][2];
            #pragma unroll
            for (int i = 0; i < 4; i++) {
                uint32_t ro = (i * 16 + arow) * KP2E + kk + akof;
                ldm_x4(ah[i], sb + ro * 2);
                ldm_x4(al[i], sb + SM2_AL + ro * 2);
            }
            #pragma unroll
            for (int j = 0; j < 2; j++) {
                uint32_t ro = (n_w + j * 8 + brow) * KP2E + kk + bkof;
                ldm_x2(bh[j], sb + SM2_BH + ro * 2);
                ldm_x2(bl[j], sb + SM2_BL + ro * 2);
            }
            #pragma unroll
            for (int i = 0; i < 4; i++)
                #pragma unroll
                for (int j = 0; j < 2; j++) {
                    mma16816(acc[i][j], ah[i], bh[j]);
                    mma16816(acc[i][j], ah[i], bl[j]);
                    mma16816(acc[i][j], al[i], bh[j]);
                }
        }
    }

    float* dst = g_ENT2[kz];
    #pragma unroll
    for (int i = 0; i < 4; i++) {
        int row = rb + i * 16 + (lane >> 2);
        #pragma unroll
        for (int j = 0; j < 2; j++) {
            int col = n0 + n_w + j * 8 + (lane & 3) * 2;
            float bb0 = 0.f, bb1 = 0.f;
            if (kz == 0) { bb0 = __ldg(b2 + col); bb1 = __ldg(b2 + col + 1); }
            float2 o0 = make_float2(acc[i][j][0] + bb0, acc[i][j][1] + bb1);
            float2 o1 = make_float2(acc[i][j][2] + bb0, acc[i][j][3] + bb1);
            *(float2*)(dst + row * H_ + col)       = o0;
            *(float2*)(dst + (row + 8) * H_ + col) = o1;
        }
    }
}

// ---------------------------------------------------------------------------
// K3 v3: persistent grid (1184 blocks = 148 SMs x 8) with cross-iteration id
// prefetch. Per-warp masks (no barrier), streaming output stores.
// Each block grid-strides over row-quads; next quad's ids are loaded during
// the current quad's FMA/stores, so the id->gather chain never runs cold.
// ---------------------------------------------------------------------------
__global__ void __launch_bounds__(192, 8) k3_fuse(const int*   __restrict__ ids,
                                                  const float* __restrict__ mask,
                                                  const float* __restrict__ we,
                                                  float*       __restrict__ out) {
    const int tid  = threadIdx.x;
    const int lane = tid & 31;
    const int e_ln  = lane >> 2;
    const int rr_ln = lane & 3;
    const float4* __restrict__ we4  = (const float4*)we;
    float4*       __restrict__ out4 = (float4*)out;

    const int stride = K3_BLOCKS;
    int q = blockIdx.x;

    // Prologue: ids for first quad
    int id0, id1, id2, id3;
    {
        int row0 = (q >> 7) * S_ + ((q & 127) << 2);
        id0 = __ldg(ids + row0 + 0);
        id1 = __ldg(ids + row0 + 1);
        id2 = __ldg(ids + row0 + 2);
        id3 = __ldg(ids + row0 + 3);
    }

    while (q < 4096) {
        const int b    = q >> 7;
        const int s0   = (q & 127) << 2;
        const int row0 = b * S_ + s0;

        // Fire the 4 independent gathers with the prefetched ids
        float4 v0 = we4[(long long)id0 * (H_ / 4) + tid];
        float4 v1 = we4[(long long)id1 * (H_ / 4) + tid];
        float4 v2 = we4[(long long)id2 * (H_ / 4) + tid];
        float4 v3 = we4[(long long)id3 * (H_ / 4) + tid];

        // Per-warp mask handling (independent of gathers)
        const float mval = __ldg(mask + (b * E_ + e_ln) * S_ + s0 + rr_ln);
        const unsigned flag = __ballot_sync(0xffffffffu, mval != 0.0f);

        // Prefetch next quad's ids (overlaps FMA + stores below)
        const int qn = q + stride;
        int n0i = 0, n1i = 0, n2i = 0, n3i = 0;
        if (qn < 4096) {
            int rown = (qn >> 7) * S_ + ((qn & 127) << 2);
            n0i = __ldg(ids + rown + 0);
            n1i = __ldg(ids + rown + 1);
            n2i = __ldg(ids + rown + 2);
            n3i = __ldg(ids + rown + 3);
        }

        if (flag) {
            #pragma unroll
            for (int e = 0; e < E_; e++) {
                const unsigned f4 = (flag >> (e * 4)) & 0xFu;
                if (f4) {
                    const int idx = (b * E_ + e) * (H_ / 4) + tid;
                    float4 p  = ((const float4*)g_ENT2[0])[idx];
                    float4 p1 = ((const float4*)g_ENT2[1])[idx];
                    p.x += p1.x; p.y += p1.y; p.z += p1.z; p.w += p1.w;
                    const float m0 = __shfl_sync(0xffffffffu, mval, e * 4 + 0);
                    const float m1 = __shfl_sync(0xffffffffu, mval, e * 4 + 1);
                    const float m2 = __shfl_sync(0xffffffffu, mval, e * 4 + 2);
                    const float m3 = __shfl_sync(0xffffffffu, mval, e * 4 + 3);
                    if (f4 & 1u) {
                        v0.x = fmaf(m0, p.x, v0.x); v0.y = fmaf(m0, p.y, v0.y);
                        v0.z = fmaf(m0, p.z, v0.z); v0.w = fmaf(m0, p.w, v0.w); }
                    if (f4 & 2u) {
                        v1.x = fmaf(m1, p.x, v1.x); v1.y = fmaf(m1, p.y, v1.y);
                        v1.z = fmaf(m1, p.z, v1.z); v1.w = fmaf(m1, p.w, v1.w); }
                    if (f4 & 4u) {
                        v2.x = fmaf(m2, p.x, v2.x); v2.y = fmaf(m2, p.y, v2.y);
                        v2.z = fmaf(m2, p.z, v2.z); v2.w = fmaf(m2, p.w, v2.w); }
                    if (f4 & 8u) {
                        v3.x = fmaf(m3, p.x, v3.x); v3.y = fmaf(m3, p.y, v3.y);
                        v3.z = fmaf(m3, p.z, v3.z); v3.w = fmaf(m3, p.w, v3.w); }
                }
            }
        }

        __stcs(out4 + (long long)(row0 + 0) * (H_ / 4) + tid, v0);
        __stcs(out4 + (long long)(row0 + 1) * (H_ / 4) + tid, v1);
        __stcs(out4 + (long long)(row0 + 2) * (H_ / 4) + tid, v2);
        __stcs(out4 + (long long)(row0 + 3) * (H_ / 4) + tid, v3);

        id0 = n0i; id1 = n1i; id2 = n2i; id3 = n3i;
        q = qn;
    }
}

// ---------------------------------------------------------------------------
extern "C" void kernel_launch(void* const* d_in, const int* in_sizes, int n_in,
                              void* d_out, int out_size) {
    const int*   ids  = (const int*)  d_in[0];
    const float* X    = (const float*)d_in[1];
    const float* msk  = (const float*)d_in[2];
    const float* we   = (const float*)d_in[3];
    const float* W1   = (const float*)d_in[4];
    const float* b1   = (const float*)d_in[5];
    const float* W2   = (const float*)d_in[6];
    const float* b2   = (const float*)d_in[7];
    float* out = (float*)d_out;

    cudaFuncSetAttribute(k1_mma, cudaFuncAttributeMaxDynamicSharedMemorySize, SMEM1);
    cudaFuncSetAttribute(k2_mma, cudaFuncAttributeMaxDynamicSharedMemorySize, SMEM2);

    kprep<<<928, dim3(32, 8)>>>(W2, W1, X);
    k1_mma<<<dim3(8, 8), 128, SMEM1>>>(b1);
    k2_mma<<<dim3(4, 12, 2), 128, SMEM2>>>(b2);
    k3_fuse<<<K3_BLOCKS, 192>>>(ids, msk, we, out);
}